// round 15
// baseline (speedup 1.0000x reference)
#include <cuda_runtime.h>
#include <stdint.h>

#define NN     100000
#define INC    256
#define HIDC   64
#define OC     40
#define MAXD1  64
#define MAXD2  80
#define OVFMAX 65536

static __device__ float g_g1[(size_t)NN * OC];
static __device__ float g_g2[(size_t)NN * OC];
static __device__ int   g_cnt1[NN];
static __device__ int   g_cnt2[NN];
static __device__ int2  g_slot1[(size_t)NN * MAXD1];   // (col, val-bits)
static __device__ int2  g_slot2[(size_t)NN * MAXD2];
static __device__ int   g_ovf_n;
static __device__ int4  g_ovf[OVFMAX];                 // (graph, row, col, val-bits)

__device__ __forceinline__ uint32_t to_tf32(float f) {
    uint32_t r;
    asm("cvt.rna.tf32.f32 %0, %1;" : "=r"(r) : "f"(f));
    return r;
}

// Dynamic smem layout (uint32 indices):
//   WB  [128][68] at 0        (fc_out_w as [c][k] tf32, pad cols >=120 zero)
//   XS  [128][36] at 8704     (phase 1 x tile)
//   WS  [64][36]  at 13312    (phase 1 w tile)
//   H0S [128][68] at 8704     (phase 2: overlays XS/WS)
#define OFF_WB  0
#define OFF_XS  8704
#define OFF_WS  13312
#define OFF_H0S 8704
#define SMEM_UINTS 17408
#define SMEM_BYTES (SMEM_UINTS * 4)

// ---------------------------------------------------------------------------
// FUSED: x[128,256] -(MMA1 tf32)-> h0[128,64] (smem, tf32)
//        -(MMA2 tf32)-> [out | g1 | g2][128,120] (+bias on out)
// ---------------------------------------------------------------------------
__global__ __launch_bounds__(256) void fused_gemm(const float* __restrict__ x,
                                                  const float* __restrict__ w1,
                                                  const float* __restrict__ w2,
                                                  const float* __restrict__ bias,
                                                  float* __restrict__ out) {
    extern __shared__ uint32_t sm[];
    uint32_t* WB  = sm + OFF_WB;
    uint32_t* XS  = sm + OFF_XS;
    uint32_t* WS  = sm + OFF_WS;
    uint32_t* H0S = sm + OFF_H0S;

    const int tid  = threadIdx.x;
    const int wid  = tid >> 5;
    const int lane = tid & 31;
    const int wm   = wid & 3;
    const int wn   = wid >> 2;
    const int grp  = lane >> 2;
    const int tig  = lane & 3;
    const int row0 = blockIdx.x * 128;

    // stage WB: [c][k] tf32 from fc_out_w; c<120 real, else 0
#pragma unroll
    for (int q = 0; q < 8; q++) {
        int f  = tid + q * 256;
        int c  = f >> 4;
        int k4 = f & 15;
        uint4 t = make_uint4(0u, 0u, 0u, 0u);
        if (c < 120) {
            int o = c % 40;
            int s = c / 40;
            float4 v = __ldg(reinterpret_cast<const float4*>(
                w2 + (size_t)o * 192 + s * 64 + k4 * 4));
            t = make_uint4(to_tf32(v.x), to_tf32(v.y), to_tf32(v.z), to_tf32(v.w));
        }
        *reinterpret_cast<uint4*>(&WB[c * 68 + k4 * 4]) = t;
    }

    // -------------------- phase 1: h0 = x @ w1^T --------------------
    float c1[2][4][4];
#pragma unroll
    for (int mt = 0; mt < 2; mt++)
#pragma unroll
        for (int nt = 0; nt < 4; nt++)
#pragma unroll
            for (int j = 0; j < 4; j++) c1[mt][nt][j] = 0.f;

    for (int k0 = 0; k0 < INC; k0 += 32) {
#pragma unroll
        for (int q = 0; q < 4; q++) {
            int f  = tid + q * 256;
            int k4 = f & 7;
            int r  = f >> 3;
            int gr = min(row0 + r, NN - 1);
            float4 v = __ldg(reinterpret_cast<const float4*>(x + (size_t)gr * INC + k0 + k4 * 4));
            uint4 t = make_uint4(to_tf32(v.x), to_tf32(v.y), to_tf32(v.z), to_tf32(v.w));
            *reinterpret_cast<uint4*>(&XS[r * 36 + k4 * 4]) = t;
        }
#pragma unroll
        for (int q = 0; q < 2; q++) {
            int f  = tid + q * 256;
            int k4 = f & 7;
            int n  = f >> 3;
            float4 v = __ldg(reinterpret_cast<const float4*>(w1 + (size_t)n * INC + k0 + k4 * 4));
            uint4 t = make_uint4(to_tf32(v.x), to_tf32(v.y), to_tf32(v.z), to_tf32(v.w));
            *reinterpret_cast<uint4*>(&WS[n * 36 + k4 * 4]) = t;
        }
        __syncthreads();

#pragma unroll
        for (int s = 0; s < 4; s++) {
            const int kk = s * 8;
            uint32_t a[2][4], b[4][2];
#pragma unroll
            for (int mt = 0; mt < 2; mt++) {
                int m = wm * 32 + mt * 16;
                a[mt][0] = XS[(m + grp) * 36 + kk + tig];
                a[mt][1] = XS[(m + 8 + grp) * 36 + kk + tig];
                a[mt][2] = XS[(m + grp) * 36 + kk + tig + 4];
                a[mt][3] = XS[(m + 8 + grp) * 36 + kk + tig + 4];
            }
#pragma unroll
            for (int nt = 0; nt < 4; nt++) {
                int n = wn * 32 + nt * 8;
                b[nt][0] = WS[(n + grp) * 36 + kk + tig];
                b[nt][1] = WS[(n + grp) * 36 + kk + tig + 4];
            }
#pragma unroll
            for (int mt = 0; mt < 2; mt++)
#pragma unroll
                for (int nt = 0; nt < 4; nt++) {
                    asm volatile(
                        "mma.sync.aligned.m16n8k8.row.col.f32.tf32.tf32.f32 "
                        "{%0,%1,%2,%3}, {%4,%5,%6,%7}, {%8,%9}, {%0,%1,%2,%3};"
                        : "+f"(c1[mt][nt][0]), "+f"(c1[mt][nt][1]),
                          "+f"(c1[mt][nt][2]), "+f"(c1[mt][nt][3])
                        : "r"(a[mt][0]), "r"(a[mt][1]), "r"(a[mt][2]), "r"(a[mt][3]),
                          "r"(b[nt][0]), "r"(b[nt][1]));
                }
        }
        __syncthreads();
    }

    // h0 frags -> H0S (tf32)
#pragma unroll
    for (int mt = 0; mt < 2; mt++) {
        int r_lo = wm * 32 + mt * 16 + grp;
        int r_hi = r_lo + 8;
#pragma unroll
        for (int nt = 0; nt < 4; nt++) {
            int col = wn * 32 + nt * 8 + 2 * tig;
            *reinterpret_cast<uint2*>(&H0S[r_lo * 68 + col]) =
                make_uint2(to_tf32(c1[mt][nt][0]), to_tf32(c1[mt][nt][1]));
            *reinterpret_cast<uint2*>(&H0S[r_hi * 68 + col]) =
                make_uint2(to_tf32(c1[mt][nt][2]), to_tf32(c1[mt][nt][3]));
        }
    }
    __syncthreads();

    // -------------------- phase 2: [out|g1|g2] = h0 @ WB^T --------------------
    float c2[2][8][4];
#pragma unroll
    for (int mt = 0; mt < 2; mt++)
#pragma unroll
        for (int nt = 0; nt < 8; nt++)
#pragma unroll
            for (int j = 0; j < 4; j++) c2[mt][nt][j] = 0.f;

#pragma unroll
    for (int s = 0; s < 8; s++) {
        const int kk = s * 8;
        uint32_t a[2][4], b[8][2];
#pragma unroll
        for (int mt = 0; mt < 2; mt++) {
            int m = wm * 32 + mt * 16;
            a[mt][0] = H0S[(m + grp) * 68 + kk + tig];
            a[mt][1] = H0S[(m + 8 + grp) * 68 + kk + tig];
            a[mt][2] = H0S[(m + grp) * 68 + kk + tig + 4];
            a[mt][3] = H0S[(m + 8 + grp) * 68 + kk + tig + 4];
        }
#pragma unroll
        for (int nt = 0; nt < 8; nt++) {
            int n = wn * 64 + nt * 8;
            b[nt][0] = WB[(n + grp) * 68 + kk + tig];
            b[nt][1] = WB[(n + grp) * 68 + kk + tig + 4];
        }
#pragma unroll
        for (int mt = 0; mt < 2; mt++)
#pragma unroll
            for (int nt = 0; nt < 8; nt++) {
                asm volatile(
                    "mma.sync.aligned.m16n8k8.row.col.f32.tf32.tf32.f32 "
                    "{%0,%1,%2,%3}, {%4,%5,%6,%7}, {%8,%9}, {%0,%1,%2,%3};"
                    : "+f"(c2[mt][nt][0]), "+f"(c2[mt][nt][1]),
                      "+f"(c2[mt][nt][2]), "+f"(c2[mt][nt][3])
                    : "r"(a[mt][0]), "r"(a[mt][1]), "r"(a[mt][2]), "r"(a[mt][3]),
                      "r"(b[nt][0]), "r"(b[nt][1]));
            }
    }

    // epilogue (n8-tiles never straddle 40/80/120 boundaries)
#pragma unroll
    for (int nt = 0; nt < 8; nt++) {
        int col = wn * 64 + nt * 8 + 2 * tig;
        if (col >= 120) continue;
        int seg = col / 40;
        int cb  = col - seg * 40;
        float* base = (seg == 0) ? out : (seg == 1) ? g_g1 : g_g2;
        float b0 = 0.f, b1v = 0.f;
        if (seg == 0) {
            b0  = __ldg(bias + cb);
            b1v = __ldg(bias + cb + 1);
        }
#pragma unroll
        for (int mt = 0; mt < 2; mt++) {
            int r_lo = row0 + wm * 32 + mt * 16 + grp;
            int r_hi = r_lo + 8;
            if (r_lo < NN)
                *reinterpret_cast<float2*>(base + (size_t)r_lo * OC + cb) =
                    make_float2(c2[mt][nt][0] + b0, c2[mt][nt][1] + b1v);
            if (r_hi < NN)
                *reinterpret_cast<float2*>(base + (size_t)r_hi * OC + cb) =
                    make_float2(c2[mt][nt][2] + b0, c2[mt][nt][3] + b1v);
        }
    }
}

// ---------------------------------------------------------------------------
// Binning: zero counters -> scatter (8 edges/thread, vectorized loads).
// ---------------------------------------------------------------------------
__global__ void zero_cnt() {
    int i = blockIdx.x * blockDim.x + threadIdx.x;
    if (i < NN)          g_cnt1[i] = 0;
    else if (i < 2 * NN) g_cnt2[i - NN] = 0;
    if (i == 0) g_ovf_n = 0;
}

__device__ __forceinline__ void scat1(int r, int c, float vf, int2* slots,
                                      int* cnt, int maxd, int gflag) {
    int v = __float_as_int(vf);
    int p = atomicAdd(&cnt[r], 1);
    if (p < maxd) {
        slots[(size_t)r * maxd + p] = make_int2(c, v);
    } else {
        int o = atomicAdd(&g_ovf_n, 1);
        if (o < OVFMAX) g_ovf[o] = make_int4(gflag, r, c, v);
    }
}

__global__ void scatter(const int* __restrict__ r1, const int* __restrict__ c1,
                        const float* __restrict__ v1, int E1,
                        const int* __restrict__ r2, const int* __restrict__ c2,
                        const float* __restrict__ v2, int E2) {
    int t = blockIdx.x * blockDim.x + threadIdx.x;
    int q1 = (E1 + 7) >> 3;
    int q2 = (E2 + 7) >> 3;
    const int* R; const int* C; const float* V;
    int2* slots; int* cnt; int maxd, gflag, E, base;
    if (t < q1) {
        R = r1; C = c1; V = v1; E = E1; base = t * 8;
        slots = g_slot1; cnt = g_cnt1; maxd = MAXD1; gflag = 0;
    } else if (t < q1 + q2) {
        R = r2; C = c2; V = v2; E = E2; base = (t - q1) * 8;
        slots = g_slot2; cnt = g_cnt2; maxd = MAXD2; gflag = 1;
    } else return;

    if (base + 8 <= E) {
        int4   ra = __ldg(reinterpret_cast<const int4*>(R + base));
        int4   rb = __ldg(reinterpret_cast<const int4*>(R + base + 4));
        int4   ca = __ldg(reinterpret_cast<const int4*>(C + base));
        int4   cb = __ldg(reinterpret_cast<const int4*>(C + base + 4));
        float4 va = __ldg(reinterpret_cast<const float4*>(V + base));
        float4 vb = __ldg(reinterpret_cast<const float4*>(V + base + 4));
        scat1(ra.x, ca.x, va.x, slots, cnt, maxd, gflag);
        scat1(ra.y, ca.y, va.y, slots, cnt, maxd, gflag);
        scat1(ra.z, ca.z, va.z, slots, cnt, maxd, gflag);
        scat1(ra.w, ca.w, va.w, slots, cnt, maxd, gflag);
        scat1(rb.x, cb.x, vb.x, slots, cnt, maxd, gflag);
        scat1(rb.y, cb.y, vb.y, slots, cnt, maxd, gflag);
        scat1(rb.z, cb.z, vb.z, slots, cnt, maxd, gflag);
        scat1(rb.w, cb.w, vb.w, slots, cnt, maxd, gflag);
    } else {
        for (int j = base; j < E; j++)
            scat1(__ldg(R + j), __ldg(C + j), __ldg(V + j), slots, cnt, maxd, gflag);
    }
}

// ---------------------------------------------------------------------------
// GATHER: 2 warps per row (one per graph). Warp: 3 edges x 10 float4-lanes.
// Unroll-4 (12 edges per trip, 4 independent gather chains in flight).
// Capture-first 3-way shfl combine, then one 10-lane red.v4.
// ---------------------------------------------------------------------------
__global__ __launch_bounds__(256) void gather(float* __restrict__ out) {
    const int w = (int)((blockIdx.x * blockDim.x + threadIdx.x) >> 5);
    if (w >= 2 * NN) return;
    const int r = w >> 1;
    const int g = w & 1;

    const int2*  slots;
    const float* G;
    int cnt;
    if (g == 0) {
        slots = g_slot1 + (size_t)r * MAXD1;
        G     = g_g1;
        cnt   = min(__ldg(&g_cnt1[r]), MAXD1);
    } else {
        slots = g_slot2 + (size_t)r * MAXD2;
        G     = g_g2;
        cnt   = min(__ldg(&g_cnt2[r]), MAXD2);
    }

    const int lane = threadIdx.x & 31;
    const int grp  = lane / 10;
    const int slot = lane - grp * 10;
    const bool act = lane < 30;

    float4 acc = make_float4(0.f, 0.f, 0.f, 0.f);
    if (act) {
        int e = grp;
        for (; e + 9 < cnt; e += 12) {
            int2 s0 = __ldg(slots + e);
            int2 s1 = __ldg(slots + e + 3);
            int2 s2 = __ldg(slots + e + 6);
            int2 s3 = __ldg(slots + e + 9);
            float4 h0 = __ldg(reinterpret_cast<const float4*>(
                              G + (size_t)s0.x * OC + slot * 4));
            float4 h1 = __ldg(reinterpret_cast<const float4*>(
                              G + (size_t)s1.x * OC + slot * 4));
            float4 h2 = __ldg(reinterpret_cast<const float4*>(
                              G + (size_t)s2.x * OC + slot * 4));
            float4 h3 = __ldg(reinterpret_cast<const float4*>(
                              G + (size_t)s3.x * OC + slot * 4));
            float v0 = __int_as_float(s0.y);
            float v1 = __int_as_float(s1.y);
            float v2 = __int_as_float(s2.y);
            float v3 = __int_as_float(s3.y);
            acc.x += v0 * h0.x + v1 * h1.x + v2 * h2.x + v3 * h3.x;
            acc.y += v0 * h0.y + v1 * h1.y + v2 * h2.y + v3 * h3.y;
            acc.z += v0 * h0.z + v1 * h1.z + v2 * h2.z + v3 * h3.z;
            acc.w += v0 * h0.w + v1 * h1.w + v2 * h2.w + v3 * h3.w;
        }
        for (; e < cnt; e += 3) {
            int2 s0 = __ldg(slots + e);
            float4 h0 = __ldg(reinterpret_cast<const float4*>(
                              G + (size_t)s0.x * OC + slot * 4));
            float v0 = __int_as_float(s0.y);
            acc.x += v0 * h0.x; acc.y += v0 * h0.y;
            acc.z += v0 * h0.z; acc.w += v0 * h0.w;
        }
    }
    float4 b1, b2;
    b1.x = __shfl_down_sync(0xffffffffu, acc.x, 10);
    b1.y = __shfl_down_sync(0xffffffffu, acc.y, 10);
    b1.z = __shfl_down_sync(0xffffffffu, acc.z, 10);
    b1.w = __shfl_down_sync(0xffffffffu, acc.w, 10);
    b2.x = __shfl_down_sync(0xffffffffu, acc.x, 20);
    b2.y = __shfl_down_sync(0xffffffffu, acc.y, 20);
    b2.z = __shfl_down_sync(0xffffffffu, acc.z, 20);
    b2.w = __shfl_down_sync(0xffffffffu, acc.w, 20);

    if (lane < 10) {
        float* dst = out + (size_t)r * OC + slot * 4;
        float4 s = make_float4(acc.x + b1.x + b2.x, acc.y + b1.y + b2.y,
                               acc.z + b1.z + b2.z, acc.w + b1.w + b2.w);
        asm volatile("red.global.add.v4.f32 [%0], {%1,%2,%3,%4};"
                     :: "l"(dst), "f"(s.x), "f"(s.y), "f"(s.z), "f"(s.w)
                     : "memory");
    }
}

// ---------------------------------------------------------------------------
// FIXUP: process overflow edges (normally zero of them).
// ---------------------------------------------------------------------------
__global__ void fixup(float* __restrict__ out) {
    int n = g_ovf_n;
    if (n > OVFMAX) n = OVFMAX;
    for (int i = threadIdx.x; i < n; i += blockDim.x) {
        int4 e = g_ovf[i];
        const float* G = e.x ? g_g2 : g_g1;
        float v = __int_as_float(e.w);
        for (int j = 0; j < OC; j++) {
            float p = v * G[(size_t)e.z * OC + j];
            asm volatile("red.global.add.f32 [%0], %1;"
                         :: "l"(out + (size_t)e.y * OC + j), "f"(p) : "memory");
        }
    }
}

// ---------------------------------------------------------------------------
// Launch: zero -> scatter -> fused_gemm -> gather -> fixup
// ---------------------------------------------------------------------------
extern "C" void kernel_launch(void* const* d_in, const int* in_sizes, int n_in,
                              void* d_out, int out_size) {
    const float* x   = (const float*)d_in[0];
    const int*   a1r = (const int*)  d_in[2];
    const int*   a1c = (const int*)  d_in[3];
    const float* a1v = (const float*)d_in[4];
    const int*   a2r = (const int*)  d_in[5];
    const int*   a2c = (const int*)  d_in[6];
    const float* a2v = (const float*)d_in[7];
    const float* w1  = (const float*)d_in[8];
    const float* w2  = (const float*)d_in[9];
    const float* b2  = (const float*)d_in[10];
    float* out = (float*)d_out;
    const int E1 = in_sizes[4];
    const int E2 = in_sizes[7];

    cudaFuncSetAttribute(fused_gemm, cudaFuncAttributeMaxDynamicSharedMemorySize,
                         SMEM_BYTES);

    zero_cnt<<<(2 * NN + 255) / 256, 256>>>();
    {
        int q = ((E1 + 7) >> 3) + ((E2 + 7) >> 3);
        scatter<<<(q + 255) / 256, 256>>>(a1r, a1c, a1v, E1, a2r, a2c, a2v, E2);
    }
    fused_gemm<<<(NN + 127) / 128, 256, SMEM_BYTES>>>(x, w1, w2, b2, out);
    gather<<<(2 * NN * 32 + 255) / 256, 256>>>(out);
    fixup<<<1, 256>>>(out);
}

// round 16
// speedup vs baseline: 1.0501x; 1.0501x over previous
#include <cuda_runtime.h>
#include <stdint.h>

#define NN     100000
#define INC    256
#define HIDC   64
#define OC     40
#define MAXD1  64
#define MAXD2  80
#define OVFMAX 65536

static __device__ float g_g1[(size_t)NN * OC];
static __device__ float g_g2[(size_t)NN * OC];
static __device__ int   g_cnt1[NN];
static __device__ int   g_cnt2[NN];
static __device__ int2  g_slot1[(size_t)NN * MAXD1];   // (col, val-bits)
static __device__ int2  g_slot2[(size_t)NN * MAXD2];
static __device__ int   g_ovf_n;
static __device__ int4  g_ovf[OVFMAX];                 // (graph, row, col, val-bits)

__device__ __forceinline__ uint32_t to_tf32(float f) {
    uint32_t r;
    asm("cvt.rna.tf32.f32 %0, %1;" : "=r"(r) : "f"(f));
    return r;
}

// Dynamic smem layout (uint32 indices):
//   WB  [128][68] at 0        (fc_out_w as [c][k] tf32, pad cols >=120 zero)
//   XS  [128][36] at 8704     (phase 1 x tile)
//   WS  [64][36]  at 13312    (phase 1 w tile)
//   H0S [128][68] at 8704     (phase 2: overlays XS/WS)
#define OFF_WB  0
#define OFF_XS  8704
#define OFF_WS  13312
#define OFF_H0S 8704
#define SMEM_UINTS 17408
#define SMEM_BYTES (SMEM_UINTS * 4)

// ---------------------------------------------------------------------------
// FUSED: x[128,256] -(MMA1 tf32)-> h0[128,64] (smem, tf32)
//        -(MMA2 tf32)-> [out | g1 | g2][128,120] (+bias on out)
// ---------------------------------------------------------------------------
__global__ __launch_bounds__(256) void fused_gemm(const float* __restrict__ x,
                                                  const float* __restrict__ w1,
                                                  const float* __restrict__ w2,
                                                  const float* __restrict__ bias,
                                                  float* __restrict__ out) {
    extern __shared__ uint32_t sm[];
    uint32_t* WB  = sm + OFF_WB;
    uint32_t* XS  = sm + OFF_XS;
    uint32_t* WS  = sm + OFF_WS;
    uint32_t* H0S = sm + OFF_H0S;

    const int tid  = threadIdx.x;
    const int wid  = tid >> 5;
    const int lane = tid & 31;
    const int wm   = wid & 3;
    const int wn   = wid >> 2;
    const int grp  = lane >> 2;
    const int tig  = lane & 3;
    const int row0 = blockIdx.x * 128;

    // stage WB: [c][k] tf32 from fc_out_w; c<120 real, else 0
#pragma unroll
    for (int q = 0; q < 8; q++) {
        int f  = tid + q * 256;
        int c  = f >> 4;
        int k4 = f & 15;
        uint4 t = make_uint4(0u, 0u, 0u, 0u);
        if (c < 120) {
            int o = c % 40;
            int s = c / 40;
            float4 v = __ldg(reinterpret_cast<const float4*>(
                w2 + (size_t)o * 192 + s * 64 + k4 * 4));
            t = make_uint4(to_tf32(v.x), to_tf32(v.y), to_tf32(v.z), to_tf32(v.w));
        }
        *reinterpret_cast<uint4*>(&WB[c * 68 + k4 * 4]) = t;
    }

    // -------------------- phase 1: h0 = x @ w1^T --------------------
    float c1[2][4][4];
#pragma unroll
    for (int mt = 0; mt < 2; mt++)
#pragma unroll
        for (int nt = 0; nt < 4; nt++)
#pragma unroll
            for (int j = 0; j < 4; j++) c1[mt][nt][j] = 0.f;

    for (int k0 = 0; k0 < INC; k0 += 32) {
#pragma unroll
        for (int q = 0; q < 4; q++) {
            int f  = tid + q * 256;
            int k4 = f & 7;
            int r  = f >> 3;
            int gr = min(row0 + r, NN - 1);
            float4 v = __ldg(reinterpret_cast<const float4*>(x + (size_t)gr * INC + k0 + k4 * 4));
            uint4 t = make_uint4(to_tf32(v.x), to_tf32(v.y), to_tf32(v.z), to_tf32(v.w));
            *reinterpret_cast<uint4*>(&XS[r * 36 + k4 * 4]) = t;
        }
#pragma unroll
        for (int q = 0; q < 2; q++) {
            int f  = tid + q * 256;
            int k4 = f & 7;
            int n  = f >> 3;
            float4 v = __ldg(reinterpret_cast<const float4*>(w1 + (size_t)n * INC + k0 + k4 * 4));
            uint4 t = make_uint4(to_tf32(v.x), to_tf32(v.y), to_tf32(v.z), to_tf32(v.w));
            *reinterpret_cast<uint4*>(&WS[n * 36 + k4 * 4]) = t;
        }
        __syncthreads();

#pragma unroll
        for (int s = 0; s < 4; s++) {
            const int kk = s * 8;
            uint32_t a[2][4], b[4][2];
#pragma unroll
            for (int mt = 0; mt < 2; mt++) {
                int m = wm * 32 + mt * 16;
                a[mt][0] = XS[(m + grp) * 36 + kk + tig];
                a[mt][1] = XS[(m + 8 + grp) * 36 + kk + tig];
                a[mt][2] = XS[(m + grp) * 36 + kk + tig + 4];
                a[mt][3] = XS[(m + 8 + grp) * 36 + kk + tig + 4];
            }
#pragma unroll
            for (int nt = 0; nt < 4; nt++) {
                int n = wn * 32 + nt * 8;
                b[nt][0] = WS[(n + grp) * 36 + kk + tig];
                b[nt][1] = WS[(n + grp) * 36 + kk + tig + 4];
            }
#pragma unroll
            for (int mt = 0; mt < 2; mt++)
#pragma unroll
                for (int nt = 0; nt < 4; nt++) {
                    asm volatile(
                        "mma.sync.aligned.m16n8k8.row.col.f32.tf32.tf32.f32 "
                        "{%0,%1,%2,%3}, {%4,%5,%6,%7}, {%8,%9}, {%0,%1,%2,%3};"
                        : "+f"(c1[mt][nt][0]), "+f"(c1[mt][nt][1]),
                          "+f"(c1[mt][nt][2]), "+f"(c1[mt][nt][3])
                        : "r"(a[mt][0]), "r"(a[mt][1]), "r"(a[mt][2]), "r"(a[mt][3]),
                          "r"(b[nt][0]), "r"(b[nt][1]));
                }
        }
        __syncthreads();
    }

    // h0 frags -> H0S (tf32)
#pragma unroll
    for (int mt = 0; mt < 2; mt++) {
        int r_lo = wm * 32 + mt * 16 + grp;
        int r_hi = r_lo + 8;
#pragma unroll
        for (int nt = 0; nt < 4; nt++) {
            int col = wn * 32 + nt * 8 + 2 * tig;
            *reinterpret_cast<uint2*>(&H0S[r_lo * 68 + col]) =
                make_uint2(to_tf32(c1[mt][nt][0]), to_tf32(c1[mt][nt][1]));
            *reinterpret_cast<uint2*>(&H0S[r_hi * 68 + col]) =
                make_uint2(to_tf32(c1[mt][nt][2]), to_tf32(c1[mt][nt][3]));
        }
    }
    __syncthreads();

    // -------------------- phase 2: [out|g1|g2] = h0 @ WB^T --------------------
    float c2[2][8][4];
#pragma unroll
    for (int mt = 0; mt < 2; mt++)
#pragma unroll
        for (int nt = 0; nt < 8; nt++)
#pragma unroll
            for (int j = 0; j < 4; j++) c2[mt][nt][j] = 0.f;

#pragma unroll
    for (int s = 0; s < 8; s++) {
        const int kk = s * 8;
        uint32_t a[2][4], b[8][2];
#pragma unroll
        for (int mt = 0; mt < 2; mt++) {
            int m = wm * 32 + mt * 16;
            a[mt][0] = H0S[(m + grp) * 68 + kk + tig];
            a[mt][1] = H0S[(m + 8 + grp) * 68 + kk + tig];
            a[mt][2] = H0S[(m + grp) * 68 + kk + tig + 4];
            a[mt][3] = H0S[(m + 8 + grp) * 68 + kk + tig + 4];
        }
#pragma unroll
        for (int nt = 0; nt < 8; nt++) {
            int n = wn * 64 + nt * 8;
            b[nt][0] = WB[(n + grp) * 68 + kk + tig];
            b[nt][1] = WB[(n + grp) * 68 + kk + tig + 4];
        }
#pragma unroll
        for (int mt = 0; mt < 2; mt++)
#pragma unroll
            for (int nt = 0; nt < 8; nt++) {
                asm volatile(
                    "mma.sync.aligned.m16n8k8.row.col.f32.tf32.tf32.f32 "
                    "{%0,%1,%2,%3}, {%4,%5,%6,%7}, {%8,%9}, {%0,%1,%2,%3};"
                    : "+f"(c2[mt][nt][0]), "+f"(c2[mt][nt][1]),
                      "+f"(c2[mt][nt][2]), "+f"(c2[mt][nt][3])
                    : "r"(a[mt][0]), "r"(a[mt][1]), "r"(a[mt][2]), "r"(a[mt][3]),
                      "r"(b[nt][0]), "r"(b[nt][1]));
            }
    }

    // epilogue (n8-tiles never straddle 40/80/120 boundaries)
#pragma unroll
    for (int nt = 0; nt < 8; nt++) {
        int col = wn * 64 + nt * 8 + 2 * tig;
        if (col >= 120) continue;
        int seg = col / 40;
        int cb  = col - seg * 40;
        float* base = (seg == 0) ? out : (seg == 1) ? g_g1 : g_g2;
        float b0 = 0.f, b1v = 0.f;
        if (seg == 0) {
            b0  = __ldg(bias + cb);
            b1v = __ldg(bias + cb + 1);
        }
#pragma unroll
        for (int mt = 0; mt < 2; mt++) {
            int r_lo = row0 + wm * 32 + mt * 16 + grp;
            int r_hi = r_lo + 8;
            if (r_lo < NN)
                *reinterpret_cast<float2*>(base + (size_t)r_lo * OC + cb) =
                    make_float2(c2[mt][nt][0] + b0, c2[mt][nt][1] + b1v);
            if (r_hi < NN)
                *reinterpret_cast<float2*>(base + (size_t)r_hi * OC + cb) =
                    make_float2(c2[mt][nt][2] + b0, c2[mt][nt][3] + b1v);
        }
    }
}

// ---------------------------------------------------------------------------
// Binning: zero counters -> scatter (4 edges/thread, vectorized loads).
// ---------------------------------------------------------------------------
__global__ void zero_cnt() {
    int i = blockIdx.x * blockDim.x + threadIdx.x;
    if (i < NN)          g_cnt1[i] = 0;
    else if (i < 2 * NN) g_cnt2[i - NN] = 0;
    if (i == 0) g_ovf_n = 0;
}

__device__ __forceinline__ void scat1(int r, int c, float vf, int2* slots,
                                      int* cnt, int maxd, int gflag) {
    int v = __float_as_int(vf);
    int p = atomicAdd(&cnt[r], 1);
    if (p < maxd) {
        slots[(size_t)r * maxd + p] = make_int2(c, v);
    } else {
        int o = atomicAdd(&g_ovf_n, 1);
        if (o < OVFMAX) g_ovf[o] = make_int4(gflag, r, c, v);
    }
}

__global__ void scatter(const int* __restrict__ r1, const int* __restrict__ c1,
                        const float* __restrict__ v1, int E1,
                        const int* __restrict__ r2, const int* __restrict__ c2,
                        const float* __restrict__ v2, int E2) {
    int t = blockIdx.x * blockDim.x + threadIdx.x;
    int q1 = (E1 + 3) >> 2;
    int q2 = (E2 + 3) >> 2;
    const int* R; const int* C; const float* V;
    int2* slots; int* cnt; int maxd, gflag, E, base;
    if (t < q1) {
        R = r1; C = c1; V = v1; E = E1; base = t * 4;
        slots = g_slot1; cnt = g_cnt1; maxd = MAXD1; gflag = 0;
    } else if (t < q1 + q2) {
        R = r2; C = c2; V = v2; E = E2; base = (t - q1) * 4;
        slots = g_slot2; cnt = g_cnt2; maxd = MAXD2; gflag = 1;
    } else return;

    if (base + 4 <= E) {
        int4   rr = __ldg(reinterpret_cast<const int4*>(R + base));
        int4   cc = __ldg(reinterpret_cast<const int4*>(C + base));
        float4 vv = __ldg(reinterpret_cast<const float4*>(V + base));
        scat1(rr.x, cc.x, vv.x, slots, cnt, maxd, gflag);
        scat1(rr.y, cc.y, vv.y, slots, cnt, maxd, gflag);
        scat1(rr.z, cc.z, vv.z, slots, cnt, maxd, gflag);
        scat1(rr.w, cc.w, vv.w, slots, cnt, maxd, gflag);
    } else {
        for (int j = base; j < E; j++)
            scat1(__ldg(R + j), __ldg(C + j), __ldg(V + j), slots, cnt, maxd, gflag);
    }
}

// ---------------------------------------------------------------------------
// GATHER: 3 warps per row: sub0 = graph1 (full), sub1/sub2 = graph2 halves.
// Warp: 3 edges x 10 float4-lanes, unroll-2 (round-14 shape). Capture-first
// 3-way shfl combine, then one 10-lane red.v4 into proj-initialized out.
// ---------------------------------------------------------------------------
__global__ __launch_bounds__(256) void gather(float* __restrict__ out) {
    const int w = (int)((blockIdx.x * blockDim.x + threadIdx.x) >> 5);
    if (w >= 3 * NN) return;
    const int r   = w / 3;
    const int sub = w - r * 3;

    const int2*  slots;
    const float* G;
    int beg, end;
    if (sub == 0) {
        slots = g_slot1 + (size_t)r * MAXD1;
        G     = g_g1;
        beg   = 0;
        end   = min(__ldg(&g_cnt1[r]), MAXD1);
    } else {
        slots = g_slot2 + (size_t)r * MAXD2;
        G     = g_g2;
        int cnt  = min(__ldg(&g_cnt2[r]), MAXD2);
        int half = (cnt + 1) >> 1;
        beg = (sub == 1) ? 0 : half;
        end = (sub == 1) ? half : cnt;
    }

    const int lane = threadIdx.x & 31;
    const int grp  = lane / 10;
    const int slot = lane - grp * 10;
    const bool act = lane < 30;

    float4 acc = make_float4(0.f, 0.f, 0.f, 0.f);
    if (act) {
        int e = beg + grp;
        for (; e + 3 < end; e += 6) {
            int2 ea = __ldg(slots + e);
            int2 eb = __ldg(slots + e + 3);
            float4 ha = __ldg(reinterpret_cast<const float4*>(
                              G + (size_t)ea.x * OC + slot * 4));
            float4 hb = __ldg(reinterpret_cast<const float4*>(
                              G + (size_t)eb.x * OC + slot * 4));
            float va = __int_as_float(ea.y);
            float vb = __int_as_float(eb.y);
            acc.x += va * ha.x + vb * hb.x;
            acc.y += va * ha.y + vb * hb.y;
            acc.z += va * ha.z + vb * hb.z;
            acc.w += va * ha.w + vb * hb.w;
        }
        if (e < end) {
            int2 ea = __ldg(slots + e);
            float4 ha = __ldg(reinterpret_cast<const float4*>(
                              G + (size_t)ea.x * OC + slot * 4));
            float va = __int_as_float(ea.y);
            acc.x += va * ha.x; acc.y += va * ha.y;
            acc.z += va * ha.z; acc.w += va * ha.w;
        }
    }
    float4 b1, b2;
    b1.x = __shfl_down_sync(0xffffffffu, acc.x, 10);
    b1.y = __shfl_down_sync(0xffffffffu, acc.y, 10);
    b1.z = __shfl_down_sync(0xffffffffu, acc.z, 10);
    b1.w = __shfl_down_sync(0xffffffffu, acc.w, 10);
    b2.x = __shfl_down_sync(0xffffffffu, acc.x, 20);
    b2.y = __shfl_down_sync(0xffffffffu, acc.y, 20);
    b2.z = __shfl_down_sync(0xffffffffu, acc.z, 20);
    b2.w = __shfl_down_sync(0xffffffffu, acc.w, 20);

    if (lane < 10) {
        float* dst = out + (size_t)r * OC + slot * 4;
        float4 s = make_float4(acc.x + b1.x + b2.x, acc.y + b1.y + b2.y,
                               acc.z + b1.z + b2.z, acc.w + b1.w + b2.w);
        asm volatile("red.global.add.v4.f32 [%0], {%1,%2,%3,%4};"
                     :: "l"(dst), "f"(s.x), "f"(s.y), "f"(s.z), "f"(s.w)
                     : "memory");
    }
}

// ---------------------------------------------------------------------------
// FIXUP: process overflow edges (normally zero of them).
// ---------------------------------------------------------------------------
__global__ void fixup(float* __restrict__ out) {
    int n = g_ovf_n;
    if (n > OVFMAX) n = OVFMAX;
    for (int i = threadIdx.x; i < n; i += blockDim.x) {
        int4 e = g_ovf[i];
        const float* G = e.x ? g_g2 : g_g1;
        float v = __int_as_float(e.w);
        for (int j = 0; j < OC; j++) {
            float p = v * G[(size_t)e.z * OC + j];
            asm volatile("red.global.add.f32 [%0], %1;"
                         :: "l"(out + (size_t)e.y * OC + j), "f"(p) : "memory");
        }
    }
}

// ---------------------------------------------------------------------------
// Launch: zero -> scatter -> fused_gemm -> gather -> fixup
// ---------------------------------------------------------------------------
extern "C" void kernel_launch(void* const* d_in, const int* in_sizes, int n_in,
                              void* d_out, int out_size) {
    const float* x   = (const float*)d_in[0];
    const int*   a1r = (const int*)  d_in[2];
    const int*   a1c = (const int*)  d_in[3];
    const float* a1v = (const float*)d_in[4];
    const int*   a2r = (const int*)  d_in[5];
    const int*   a2c = (const int*)  d_in[6];
    const float* a2v = (const float*)d_in[7];
    const float* w1  = (const float*)d_in[8];
    const float* w2  = (const float*)d_in[9];
    const float* b2  = (const float*)d_in[10];
    float* out = (float*)d_out;
    const int E1 = in_sizes[4];
    const int E2 = in_sizes[7];

    cudaFuncSetAttribute(fused_gemm, cudaFuncAttributeMaxDynamicSharedMemorySize,
                         SMEM_BYTES);

    zero_cnt<<<(2 * NN + 255) / 256, 256>>>();
    {
        int q = ((E1 + 3) >> 2) + ((E2 + 3) >> 2);
        scatter<<<(q + 255) / 256, 256>>>(a1r, a1c, a1v, E1, a2r, a2c, a2v, E2);
    }
    fused_gemm<<<(NN + 127) / 128, 256, SMEM_BYTES>>>(x, w1, w2, b2, out);
    gather<<<((3 * NN) * 32 + 255) / 256, 256>>>(out);
    fixup<<<1, 256>>>(out);
}

// round 17
// speedup vs baseline: 1.1641x; 1.1086x over previous
#include <cuda_runtime.h>
#include <stdint.h>

#define NN     100000
#define INC    256
#define HIDC   64
#define OC     40
#define MAXD1  64
#define MAXD2  80
#define OVFMAX 65536

static __device__ float g_g1[(size_t)NN * OC];
static __device__ float g_g2[(size_t)NN * OC];
static __device__ int   g_cnt1[NN];
static __device__ int   g_cnt2[NN];
static __device__ int2  g_slot1[(size_t)NN * MAXD1];   // (col, val-bits)
static __device__ int2  g_slot2[(size_t)NN * MAXD2];
static __device__ int   g_ovf_n;
static __device__ int4  g_ovf[OVFMAX];                 // (graph, row, col, val-bits)

__device__ __forceinline__ uint32_t to_tf32(float f) {
    uint32_t r;
    asm("cvt.rna.tf32.f32 %0, %1;" : "=r"(r) : "f"(f));
    return r;
}

// Dynamic smem layout (uint32 indices):
//   WB  [128][68] at 0        (fc_out_w as [c][k] tf32, pad cols >=120 zero)
//   XS  [128][36] at 8704     (phase 1 x tile)
//   WS  [64][36]  at 13312    (phase 1 w tile)
//   H0S [128][68] at 8704     (phase 2: overlays XS/WS)
#define OFF_WB  0
#define OFF_XS  8704
#define OFF_WS  13312
#define OFF_H0S 8704
#define SMEM_UINTS 17408
#define SMEM_BYTES (SMEM_UINTS * 4)

// ---------------------------------------------------------------------------
// FUSED: x[128,256] -(MMA1 tf32)-> h0[128,64] (smem, tf32)
//        -(MMA2 tf32)-> [out | g1 | g2][128,120] (+bias on out)
// Phase-1 software-pipelined: next k-chunk LDGs issued before current MMAs.
// ---------------------------------------------------------------------------
__global__ __launch_bounds__(256) void fused_gemm(const float* __restrict__ x,
                                                  const float* __restrict__ w1,
                                                  const float* __restrict__ w2,
                                                  const float* __restrict__ bias,
                                                  float* __restrict__ out) {
    extern __shared__ uint32_t sm[];
    uint32_t* WB  = sm + OFF_WB;
    uint32_t* XS  = sm + OFF_XS;
    uint32_t* WS  = sm + OFF_WS;
    uint32_t* H0S = sm + OFF_H0S;

    const int tid  = threadIdx.x;
    const int wid  = tid >> 5;
    const int lane = tid & 31;
    const int wm   = wid & 3;
    const int wn   = wid >> 2;
    const int grp  = lane >> 2;
    const int tig  = lane & 3;
    const int row0 = blockIdx.x * 128;

    // stage WB: [c][k] tf32 from fc_out_w; c<120 real, else 0
#pragma unroll
    for (int q = 0; q < 8; q++) {
        int f  = tid + q * 256;
        int c  = f >> 4;
        int k4 = f & 15;
        uint4 t = make_uint4(0u, 0u, 0u, 0u);
        if (c < 120) {
            int o = c % 40;
            int s = c / 40;
            float4 v = __ldg(reinterpret_cast<const float4*>(
                w2 + (size_t)o * 192 + s * 64 + k4 * 4));
            t = make_uint4(to_tf32(v.x), to_tf32(v.y), to_tf32(v.z), to_tf32(v.w));
        }
        *reinterpret_cast<uint4*>(&WB[c * 68 + k4 * 4]) = t;
    }

    // per-thread staging coords (fixed across chunks)
    int xk4[4], xr[4], xgr[4];
#pragma unroll
    for (int q = 0; q < 4; q++) {
        int f   = tid + q * 256;
        xk4[q]  = f & 7;
        xr[q]   = f >> 3;
        xgr[q]  = min(row0 + xr[q], NN - 1);
    }
    int wk4[2], wn_[2];
#pragma unroll
    for (int q = 0; q < 2; q++) {
        int f   = tid + q * 256;
        wk4[q]  = f & 7;
        wn_[q]  = f >> 3;
    }

    // -------------------- phase 1: h0 = x @ w1^T (pipelined) ------------
    float c1[2][4][4];
#pragma unroll
    for (int mt = 0; mt < 2; mt++)
#pragma unroll
        for (int nt = 0; nt < 4; nt++)
#pragma unroll
            for (int j = 0; j < 4; j++) c1[mt][nt][j] = 0.f;

    float4 px[4], pw[2];
    // prologue: load chunk 0
#pragma unroll
    for (int q = 0; q < 4; q++)
        px[q] = __ldg(reinterpret_cast<const float4*>(
                      x + (size_t)xgr[q] * INC + xk4[q] * 4));
#pragma unroll
    for (int q = 0; q < 2; q++)
        pw[q] = __ldg(reinterpret_cast<const float4*>(
                      w1 + (size_t)wn_[q] * INC + wk4[q] * 4));

    for (int ci = 0; ci < 8; ci++) {
        // convert + store current chunk to smem
#pragma unroll
        for (int q = 0; q < 4; q++) {
            uint4 t = make_uint4(to_tf32(px[q].x), to_tf32(px[q].y),
                                 to_tf32(px[q].z), to_tf32(px[q].w));
            *reinterpret_cast<uint4*>(&XS[xr[q] * 36 + xk4[q] * 4]) = t;
        }
#pragma unroll
        for (int q = 0; q < 2; q++) {
            uint4 t = make_uint4(to_tf32(pw[q].x), to_tf32(pw[q].y),
                                 to_tf32(pw[q].z), to_tf32(pw[q].w));
            *reinterpret_cast<uint4*>(&WS[wn_[q] * 36 + wk4[q] * 4]) = t;
        }
        __syncthreads();

        // issue next chunk's loads (latency overlapped with MMAs below)
        if (ci < 7) {
            int k0n = (ci + 1) * 32;
#pragma unroll
            for (int q = 0; q < 4; q++)
                px[q] = __ldg(reinterpret_cast<const float4*>(
                              x + (size_t)xgr[q] * INC + k0n + xk4[q] * 4));
#pragma unroll
            for (int q = 0; q < 2; q++)
                pw[q] = __ldg(reinterpret_cast<const float4*>(
                              w1 + (size_t)wn_[q] * INC + k0n + wk4[q] * 4));
        }

#pragma unroll
        for (int s = 0; s < 4; s++) {
            const int kk = s * 8;
            uint32_t a[2][4], b[4][2];
#pragma unroll
            for (int mt = 0; mt < 2; mt++) {
                int m = wm * 32 + mt * 16;
                a[mt][0] = XS[(m + grp) * 36 + kk + tig];
                a[mt][1] = XS[(m + 8 + grp) * 36 + kk + tig];
                a[mt][2] = XS[(m + grp) * 36 + kk + tig + 4];
                a[mt][3] = XS[(m + 8 + grp) * 36 + kk + tig + 4];
            }
#pragma unroll
            for (int nt = 0; nt < 4; nt++) {
                int n = wn * 32 + nt * 8;
                b[nt][0] = WS[(n + grp) * 36 + kk + tig];
                b[nt][1] = WS[(n + grp) * 36 + kk + tig + 4];
            }
#pragma unroll
            for (int mt = 0; mt < 2; mt++)
#pragma unroll
                for (int nt = 0; nt < 4; nt++) {
                    asm volatile(
                        "mma.sync.aligned.m16n8k8.row.col.f32.tf32.tf32.f32 "
                        "{%0,%1,%2,%3}, {%4,%5,%6,%7}, {%8,%9}, {%0,%1,%2,%3};"
                        : "+f"(c1[mt][nt][0]), "+f"(c1[mt][nt][1]),
                          "+f"(c1[mt][nt][2]), "+f"(c1[mt][nt][3])
                        : "r"(a[mt][0]), "r"(a[mt][1]), "r"(a[mt][2]), "r"(a[mt][3]),
                          "r"(b[nt][0]), "r"(b[nt][1]));
                }
        }
        __syncthreads();
    }

    // h0 frags -> H0S (tf32)
#pragma unroll
    for (int mt = 0; mt < 2; mt++) {
        int r_lo = wm * 32 + mt * 16 + grp;
        int r_hi = r_lo + 8;
#pragma unroll
        for (int nt = 0; nt < 4; nt++) {
            int col = wn * 32 + nt * 8 + 2 * tig;
            *reinterpret_cast<uint2*>(&H0S[r_lo * 68 + col]) =
                make_uint2(to_tf32(c1[mt][nt][0]), to_tf32(c1[mt][nt][1]));
            *reinterpret_cast<uint2*>(&H0S[r_hi * 68 + col]) =
                make_uint2(to_tf32(c1[mt][nt][2]), to_tf32(c1[mt][nt][3]));
        }
    }
    __syncthreads();

    // -------------------- phase 2: [out|g1|g2] = h0 @ WB^T ----------------
    float c2[2][8][4];
#pragma unroll
    for (int mt = 0; mt < 2; mt++)
#pragma unroll
        for (int nt = 0; nt < 8; nt++)
#pragma unroll
            for (int j = 0; j < 4; j++) c2[mt][nt][j] = 0.f;

#pragma unroll
    for (int s = 0; s < 8; s++) {
        const int kk = s * 8;
        uint32_t a[2][4], b[8][2];
#pragma unroll
        for (int mt = 0; mt < 2; mt++) {
            int m = wm * 32 + mt * 16;
            a[mt][0] = H0S[(m + grp) * 68 + kk + tig];
            a[mt][1] = H0S[(m + 8 + grp) * 68 + kk + tig];
            a[mt][2] = H0S[(m + grp) * 68 + kk + tig + 4];
            a[mt][3] = H0S[(m + 8 + grp) * 68 + kk + tig + 4];
        }
#pragma unroll
        for (int nt = 0; nt < 8; nt++) {
            int n = wn * 64 + nt * 8;
            b[nt][0] = WB[(n + grp) * 68 + kk + tig];
            b[nt][1] = WB[(n + grp) * 68 + kk + tig + 4];
        }
#pragma unroll
        for (int mt = 0; mt < 2; mt++)
#pragma unroll
            for (int nt = 0; nt < 8; nt++) {
                asm volatile(
                    "mma.sync.aligned.m16n8k8.row.col.f32.tf32.tf32.f32 "
                    "{%0,%1,%2,%3}, {%4,%5,%6,%7}, {%8,%9}, {%0,%1,%2,%3};"
                    : "+f"(c2[mt][nt][0]), "+f"(c2[mt][nt][1]),
                      "+f"(c2[mt][nt][2]), "+f"(c2[mt][nt][3])
                    : "r"(a[mt][0]), "r"(a[mt][1]), "r"(a[mt][2]), "r"(a[mt][3]),
                      "r"(b[nt][0]), "r"(b[nt][1]));
            }
    }

    // epilogue (n8-tiles never straddle 40/80/120 boundaries)
#pragma unroll
    for (int nt = 0; nt < 8; nt++) {
        int col = wn * 64 + nt * 8 + 2 * tig;
        if (col >= 120) continue;
        int seg = col / 40;
        int cb  = col - seg * 40;
        float* base = (seg == 0) ? out : (seg == 1) ? g_g1 : g_g2;
        float b0 = 0.f, b1v = 0.f;
        if (seg == 0) {
            b0  = __ldg(bias + cb);
            b1v = __ldg(bias + cb + 1);
        }
#pragma unroll
        for (int mt = 0; mt < 2; mt++) {
            int r_lo = row0 + wm * 32 + mt * 16 + grp;
            int r_hi = r_lo + 8;
            if (r_lo < NN)
                *reinterpret_cast<float2*>(base + (size_t)r_lo * OC + cb) =
                    make_float2(c2[mt][nt][0] + b0, c2[mt][nt][1] + b1v);
            if (r_hi < NN)
                *reinterpret_cast<float2*>(base + (size_t)r_hi * OC + cb) =
                    make_float2(c2[mt][nt][2] + b0, c2[mt][nt][3] + b1v);
        }
    }
}

// ---------------------------------------------------------------------------
// Binning: zero counters -> scatter (4 edges/thread, vectorized loads).
// ---------------------------------------------------------------------------
__global__ void zero_cnt() {
    int i = blockIdx.x * blockDim.x + threadIdx.x;
    if (i < NN)          g_cnt1[i] = 0;
    else if (i < 2 * NN) g_cnt2[i - NN] = 0;
    if (i == 0) g_ovf_n = 0;
}

__device__ __forceinline__ void scat1(int r, int c, float vf, int2* slots,
                                      int* cnt, int maxd, int gflag) {
    int v = __float_as_int(vf);
    int p = atomicAdd(&cnt[r], 1);
    if (p < maxd) {
        slots[(size_t)r * maxd + p] = make_int2(c, v);
    } else {
        int o = atomicAdd(&g_ovf_n, 1);
        if (o < OVFMAX) g_ovf[o] = make_int4(gflag, r, c, v);
    }
}

__global__ void scatter(const int* __restrict__ r1, const int* __restrict__ c1,
                        const float* __restrict__ v1, int E1,
                        const int* __restrict__ r2, const int* __restrict__ c2,
                        const float* __restrict__ v2, int E2) {
    int t = blockIdx.x * blockDim.x + threadIdx.x;
    int q1 = (E1 + 3) >> 2;
    int q2 = (E2 + 3) >> 2;
    const int* R; const int* C; const float* V;
    int2* slots; int* cnt; int maxd, gflag, E, base;
    if (t < q1) {
        R = r1; C = c1; V = v1; E = E1; base = t * 4;
        slots = g_slot1; cnt = g_cnt1; maxd = MAXD1; gflag = 0;
    } else if (t < q1 + q2) {
        R = r2; C = c2; V = v2; E = E2; base = (t - q1) * 4;
        slots = g_slot2; cnt = g_cnt2; maxd = MAXD2; gflag = 1;
    } else return;

    if (base + 4 <= E) {
        int4   rr = __ldg(reinterpret_cast<const int4*>(R + base));
        int4   cc = __ldg(reinterpret_cast<const int4*>(C + base));
        float4 vv = __ldg(reinterpret_cast<const float4*>(V + base));
        scat1(rr.x, cc.x, vv.x, slots, cnt, maxd, gflag);
        scat1(rr.y, cc.y, vv.y, slots, cnt, maxd, gflag);
        scat1(rr.z, cc.z, vv.z, slots, cnt, maxd, gflag);
        scat1(rr.w, cc.w, vv.w, slots, cnt, maxd, gflag);
    } else {
        for (int j = base; j < E; j++)
            scat1(__ldg(R + j), __ldg(C + j), __ldg(V + j), slots, cnt, maxd, gflag);
    }
}

// ---------------------------------------------------------------------------
// GATHER (round-14 form): 2 warps per row (one per graph). Warp: 3 edges x
// 10 float4-lanes, unroll-2. Capture-first 3-way shfl combine, 10-lane red.v4.
// ---------------------------------------------------------------------------
__global__ __launch_bounds__(256) void gather(float* __restrict__ out) {
    const int w = (int)((blockIdx.x * blockDim.x + threadIdx.x) >> 5);
    if (w >= 2 * NN) return;
    const int r = w >> 1;
    const int g = w & 1;

    const int2*  slots;
    const float* G;
    int cnt;
    if (g == 0) {
        slots = g_slot1 + (size_t)r * MAXD1;
        G     = g_g1;
        cnt   = min(__ldg(&g_cnt1[r]), MAXD1);
    } else {
        slots = g_slot2 + (size_t)r * MAXD2;
        G     = g_g2;
        cnt   = min(__ldg(&g_cnt2[r]), MAXD2);
    }

    const int lane = threadIdx.x & 31;
    const int grp  = lane / 10;
    const int slot = lane - grp * 10;
    const bool act = lane < 30;

    float4 acc = make_float4(0.f, 0.f, 0.f, 0.f);
    if (act) {
        int e = grp;
        for (; e + 3 < cnt; e += 6) {
            int2 ea = __ldg(slots + e);
            int2 eb = __ldg(slots + e + 3);
            float4 ha = __ldg(reinterpret_cast<const float4*>(
                              G + (size_t)ea.x * OC + slot * 4));
            float4 hb = __ldg(reinterpret_cast<const float4*>(
                              G + (size_t)eb.x * OC + slot * 4));
            float va = __int_as_float(ea.y);
            float vb = __int_as_float(eb.y);
            acc.x += va * ha.x + vb * hb.x;
            acc.y += va * ha.y + vb * hb.y;
            acc.z += va * ha.z + vb * hb.z;
            acc.w += va * ha.w + vb * hb.w;
        }
        if (e < cnt) {
            int2 ea = __ldg(slots + e);
            float4 ha = __ldg(reinterpret_cast<const float4*>(
                              G + (size_t)ea.x * OC + slot * 4));
            float va = __int_as_float(ea.y);
            acc.x += va * ha.x; acc.y += va * ha.y;
            acc.z += va * ha.z; acc.w += va * ha.w;
        }
    }
    float4 b1, b2;
    b1.x = __shfl_down_sync(0xffffffffu, acc.x, 10);
    b1.y = __shfl_down_sync(0xffffffffu, acc.y, 10);
    b1.z = __shfl_down_sync(0xffffffffu, acc.z, 10);
    b1.w = __shfl_down_sync(0xffffffffu, acc.w, 10);
    b2.x = __shfl_down_sync(0xffffffffu, acc.x, 20);
    b2.y = __shfl_down_sync(0xffffffffu, acc.y, 20);
    b2.z = __shfl_down_sync(0xffffffffu, acc.z, 20);
    b2.w = __shfl_down_sync(0xffffffffu, acc.w, 20);

    if (lane < 10) {
        float* dst = out + (size_t)r * OC + slot * 4;
        float4 s = make_float4(acc.x + b1.x + b2.x, acc.y + b1.y + b2.y,
                               acc.z + b1.z + b2.z, acc.w + b1.w + b2.w);
        asm volatile("red.global.add.v4.f32 [%0], {%1,%2,%3,%4};"
                     :: "l"(dst), "f"(s.x), "f"(s.y), "f"(s.z), "f"(s.w)
                     : "memory");
    }
}

// ---------------------------------------------------------------------------
// FIXUP: process overflow edges (normally zero of them).
// ---------------------------------------------------------------------------
__global__ void fixup(float* __restrict__ out) {
    int n = g_ovf_n;
    if (n > OVFMAX) n = OVFMAX;
    for (int i = threadIdx.x; i < n; i += blockDim.x) {
        int4 e = g_ovf[i];
        const float* G = e.x ? g_g2 : g_g1;
        float v = __int_as_float(e.w);
        for (int j = 0; j < OC; j++) {
            float p = v * G[(size_t)e.z * OC + j];
            asm volatile("red.global.add.f32 [%0], %1;"
                         :: "l"(out + (size_t)e.y * OC + j), "f"(p) : "memory");
        }
    }
}

// ---------------------------------------------------------------------------
// Launch: zero -> scatter -> fused_gemm -> gather -> fixup
// ---------------------------------------------------------------------------
extern "C" void kernel_launch(void* const* d_in, const int* in_sizes, int n_in,
                              void* d_out, int out_size) {
    const float* x   = (const float*)d_in[0];
    const int*   a1r = (const int*)  d_in[2];
    const int*   a1c = (const int*)  d_in[3];
    const float* a1v = (const float*)d_in[4];
    const int*   a2r = (const int*)  d_in[5];
    const int*   a2c = (const int*)  d_in[6];
    const float* a2v = (const float*)d_in[7];
    const float* w1  = (const float*)d_in[8];
    const float* w2  = (const float*)d_in[9];
    const float* b2  = (const float*)d_in[10];
    float* out = (float*)d_out;
    const int E1 = in_sizes[4];
    const int E2 = in_sizes[7];

    cudaFuncSetAttribute(fused_gemm, cudaFuncAttributeMaxDynamicSharedMemorySize,
                         SMEM_BYTES);

    zero_cnt<<<(2 * NN + 255) / 256, 256>>>();
    {
        int q = ((E1 + 3) >> 2) + ((E2 + 3) >> 2);
        scatter<<<(q + 255) / 256, 256>>>(a1r, a1c, a1v, E1, a2r, a2c, a2v, E2);
    }
    fused_gemm<<<(NN + 127) / 128, 256, SMEM_BYTES>>>(x, w1, w2, b2, out);
    gather<<<(2 * NN * 32 + 255) / 256, 256>>>(out);
    fixup<<<1, 256>>>(out);
}